// round 8
// baseline (speedup 1.0000x reference)
#include <cuda_runtime.h>

#define NX0 512
#define NY0 1024
#define N0 (NX0*NY0)
#define NX1 256
#define NY1 512
#define N1 (NX1*NY1)
#define NX2 128
#define NY2 256
#define N2 (NX2*NY2)

#define TS 16              // tile side (nodes)
#define HALO_ROWS ((TS+2)*(TS+2))   // 324
#define ROWP 36            // padded floats per halo row (conflict-free)
// dynamic smem layout (bytes)
#define OFF_W    0         // 512 u64  (4096 B)  W as channel-pairs
#define OFF_B    4096      // 16 u64   (128 B)   bias pairs
#define OFF_FC1  4224      // 160 f    (640 B)   fc1 w+b
#define OFF_FC2  4864      // 66 f -> pad 272 B
#define OFF_HALO 5136
#define SMEM_SZ  (OFF_HALO + HALO_ROWS*ROWP*4)   // 5136 + 46656 = 51792

// Scratch (device globals; allocation-free per harness rules)
__device__ float g_h  [N0*32];
__device__ float g_h1 [N1*32];
__device__ float g_h2 [N2*32];
__device__ float g_h1c[N1*32];

typedef unsigned long long u64;

__device__ __forceinline__ u64 fma2(u64 a, u64 b, u64 c) {
    u64 d; asm("fma.rn.f32x2 %0, %1, %2, %3;" : "=l"(d) : "l"(a), "l"(b), "l"(c)); return d;
}
__device__ __forceinline__ u64 mul2(u64 a, u64 b) {
    u64 d; asm("mul.rn.f32x2 %0, %1, %2;" : "=l"(d) : "l"(a), "l"(b)); return d;
}
__device__ __forceinline__ u64 pack2(float lo, float hi) {
    u64 d; asm("mov.b64 %0, {%1, %2};" : "=l"(d) : "f"(lo), "f"(hi)); return d;
}
__device__ __forceinline__ void unpack2(u64 v, float& lo, float& hi) {
    asm("mov.b64 {%0, %1}, %2;" : "=f"(lo), "=f"(hi) : "l"(v));
}

__device__ __forceinline__ float dinvf(int ix, int iy, int nx, int ny) {
    int d = 1 + (ix > 0) + (ix < nx - 1) + (iy > 0) + (iy < ny - 1);
    return rsqrtf((float)d);
}

// MODE: 0 = RAW (read rows at (hx*rs+hy*cs)*32, handles stride-2 downsample)
//       1 = FC1 (halo rows = relu(x@fc1w + fc1b), x is [N0,4])
//       2 = UPADD (halo rows = in0[p] + buffer-exact upsample gather from in1)
// FC2 : fuse final [32,2] projection, write float2 per node.
template<int MODE, bool FC2>
__global__ void __launch_bounds__(256) conv_t(
        const float* __restrict__ in0, const float* __restrict__ in1,
        float* __restrict__ out,
        const float* __restrict__ w, const float* __restrict__ b,
        int nx, int ny, int rs, int cs, int nchalf,
        const float* __restrict__ f2w, const float* __restrict__ f2b) {
    extern __shared__ __align__(16) char smem[];
    u64*   swp  = (u64*)(smem + OFF_W);
    u64*   sbp  = (u64*)(smem + OFF_B);
    float* sfc1 = (float*)(smem + OFF_FC1);
    float* sfc2 = (float*)(smem + OFF_FC2);
    float* halo = (float*)(smem + OFF_HALO);

    int t = threadIdx.x;

    // --- load weights/biases into smem ---
    {
        const u64* wp = (const u64*)w;     // row-major [32][32] -> pairs (2q,2q+1)
        swp[t]       = wp[t];
        swp[t + 256] = wp[t + 256];
        if (t < 16) sbp[t] = ((const u64*)b)[t];
        if (MODE == 1) {
            if (t < 128) sfc1[t] = w[0], sfc1[t] = 0.f;  // placeholder overwritten below
        }
    }
    if (MODE == 1) {
        // fc1 weights come through in1 (w) / f2w (b) slots: see launcher
        if (t < 128) sfc1[t]       = f2w[t];   // fc1_w [4][32]
        if (t < 32)  sfc1[128 + t] = f2b[t];   // fc1_b
    }
    if (FC2) {
        if (t < 64) sfc2[t]      = f2w[t];
        if (t < 2)  sfc2[64 + t] = f2b[t];
    }
    __syncthreads();

    // --- phase A: fill halo tile (each row loaded/computed once per block) ---
    int bx = (int)blockIdx.y;   // tile index along x
    int by = (int)blockIdx.x;   // tile index along y
    for (int r = t; r < HALO_ROWS; r += 256) {
        int hx = bx * TS - 1 + r / (TS + 2);
        int hy = by * TS - 1 + r % (TS + 2);
        float4* dst = (float4*)(halo + r * ROWP);
        if (hx < 0 || hx >= nx || hy < 0 || hy >= ny) {
            float4 z = make_float4(0.f, 0.f, 0.f, 0.f);
#pragma unroll
            for (int q = 0; q < 8; q++) dst[q] = z;
        } else if (MODE == 0) {
            const float4* src = (const float4*)(in0 + ((size_t)hx * rs + (size_t)hy * cs) * 32);
#pragma unroll
            for (int q = 0; q < 8; q++) dst[q] = src[q];
        } else if (MODE == 1) {
            float4 xi = ((const float4*)in0)[hx * NY0 + hy];
#pragma unroll
            for (int q = 0; q < 8; q++) {
                float o[4];
#pragma unroll
                for (int u = 0; u < 4; u++) {
                    int j = 4 * q + u;
                    float a = sfc1[128 + j];
                    a = fmaf(xi.x, sfc1[j],      a);
                    a = fmaf(xi.y, sfc1[32 + j], a);
                    a = fmaf(xi.z, sfc1[64 + j], a);
                    a = fmaf(xi.w, sfc1[96 + j], a);
                    o[u] = fmaxf(a, 0.f);
                }
                dst[q] = make_float4(o[0], o[1], o[2], o[3]);
            }
        } else {  // UPADD: row = in0[p] + up(in1)[p]
            int p = hx * ny + hy;
            const float4* hf4 = (const float4*)(in0 + (size_t)p * 32);
            int boff = 16 * (p & 1);
            const float4* c0 = (const float4*)(in1 + (size_t)(p >> 3) * 32 + boff);
            const float4* c1 = (const float4*)(in1 + ((size_t)nchalf + (p >> 3)) * 32 + boff);
#pragma unroll
            for (int j4 = 0; j4 < 4; j4++) {
                float4 a  = hf4[2 * j4], bb = hf4[2 * j4 + 1];
                float4 x0 = c0[j4],      x1 = c1[j4];
                dst[2 * j4]     = make_float4(a.x + x0.x, a.y + x1.x, a.z + x0.y, a.w + x1.y);
                dst[2 * j4 + 1] = make_float4(bb.x + x0.z, bb.y + x1.z, bb.z + x0.w, bb.w + x1.w);
            }
        }
    }
    __syncthreads();

    // --- phase B: one node per thread ---
    int lx = t >> 4, ly = t & 15;
    int gx = bx * TS + lx, gy = by * TS + ly;
    const u64* hbase = (const u64*)halo;   // row stride = ROWP/2 = 18 u64

    u64 aggP[16];
#pragma unroll
    for (int q = 0; q < 16; q++) aggP[q] = 0ull;

    int hcen = (lx + 1) * (TS + 2) + (ly + 1);
    float sC = dinvf(gx, gy, nx, ny);
    {
        int   hr[5] = { hcen, hcen - (TS + 2), hcen + (TS + 2), hcen - 1, hcen + 1 };
        float ss[5] = { sC,
                        dinvf(gx - 1, gy, nx, ny), dinvf(gx + 1, gy, nx, ny),
                        dinvf(gx, gy - 1, nx, ny), dinvf(gx, gy + 1, nx, ny) };
#pragma unroll
        for (int e = 0; e < 5; e++) {
            u64 sp = pack2(ss[e], ss[e]);
            const u64* rrow = hbase + hr[e] * (ROWP / 2);
#pragma unroll
            for (int q = 0; q < 16; q++) aggP[q] = fma2(sp, rrow[q], aggP[q]);
        }
    }
    {
        u64 sCp = pack2(sC, sC);
#pragma unroll
        for (int q = 0; q < 16; q++) aggP[q] = mul2(aggP[q], sCp);
    }

    u64 acc[16];
#pragma unroll
    for (int q = 0; q < 16; q++) acc[q] = sbp[q];

#pragma unroll
    for (int kp = 0; kp < 16; kp++) {
        float a0, a1; unpack2(aggP[kp], a0, a1);
        u64 a0p = pack2(a0, a0), a1p = pack2(a1, a1);
        const u64* w0 = swp + (2 * kp) * 16;
#pragma unroll
        for (int q = 0; q < 16; q++) acc[q] = fma2(a0p, w0[q], acc[q]);
#pragma unroll
        for (int q = 0; q < 16; q++) acc[q] = fma2(a1p, w0[16 + q], acc[q]);
    }

    float v[32];
#pragma unroll
    for (int q = 0; q < 16; q++) {
        float x0, x1; unpack2(acc[q], x0, x1);
        v[2 * q]     = fmaxf(x0, 0.f);
        v[2 * q + 1] = fmaxf(x1, 0.f);
    }

    if (!FC2) {
        float4* o = (float4*)(out + ((size_t)gx * ny + gy) * 32);
#pragma unroll
        for (int q = 0; q < 8; q++)
            o[q] = make_float4(v[4 * q], v[4 * q + 1], v[4 * q + 2], v[4 * q + 3]);
    } else {
        float o0 = sfc2[64], o1 = sfc2[65];
#pragma unroll
        for (int c = 0; c < 32; c++) {
            o0 = fmaf(v[c], sfc2[2 * c],     o0);
            o1 = fmaf(v[c], sfc2[2 * c + 1], o1);
        }
        ((float2*)out)[(size_t)gx * ny + gy] = make_float2(o0, o1);
    }
}

extern "C" void kernel_launch(void* const* d_in, const int* in_sizes, int n_in,
                              void* d_out, int out_size) {
    const float* x    = (const float*)d_in[0];
    // d_in[1..3]: edge_index_* — unused (regular grid, stencil is analytic)
    const float* fc1w = (const float*)d_in[4];
    const float* fc1b = (const float*)d_in[5];
    const float* w1 = (const float*)d_in[6];  const float* b1 = (const float*)d_in[7];
    const float* w2 = (const float*)d_in[8];  const float* b2 = (const float*)d_in[9];
    const float* w3 = (const float*)d_in[10]; const float* b3 = (const float*)d_in[11];
    const float* w4 = (const float*)d_in[12]; const float* b4 = (const float*)d_in[13];
    const float* w5 = (const float*)d_in[14]; const float* b5 = (const float*)d_in[15];
    const float* f2w = (const float*)d_in[16]; const float* f2b = (const float*)d_in[17];
    float* out = (float*)d_out;

    void* p;
    cudaGetSymbolAddress(&p, g_h);   float* h   = (float*)p;
    cudaGetSymbolAddress(&p, g_h1);  float* h1  = (float*)p;
    cudaGetSymbolAddress(&p, g_h2);  float* h2  = (float*)p;
    cudaGetSymbolAddress(&p, g_h1c); float* h1c = (float*)p;

    cudaFuncSetAttribute(conv_t<1, false>, cudaFuncAttributeMaxDynamicSharedMemorySize, SMEM_SZ);
    cudaFuncSetAttribute(conv_t<0, false>, cudaFuncAttributeMaxDynamicSharedMemorySize, SMEM_SZ);
    cudaFuncSetAttribute(conv_t<2, false>, cudaFuncAttributeMaxDynamicSharedMemorySize, SMEM_SZ);
    cudaFuncSetAttribute(conv_t<2, true >, cudaFuncAttributeMaxDynamicSharedMemorySize, SMEM_SZ);

    // K1: fc1 + level-0 conv (w1): x -> h
    conv_t<1, false><<<dim3(NY0 / TS, NX0 / TS), 256, SMEM_SZ>>>(
        x, nullptr, h, w1, b1, NX0, NY0, NY0, 1, 0, fc1w, fc1b);
    // K2: level-1 conv (w2), input = h downsampled (stride 2): h -> h1
    conv_t<0, false><<<dim3(NY1 / TS, NX1 / TS), 256, SMEM_SZ>>>(
        h, nullptr, h1, w2, b2, NX1, NY1, 2 * NY0, 2, 0, nullptr, nullptr);
    // K3: level-2 conv (w3), input = h1 downsampled: h1 -> h2
    conv_t<0, false><<<dim3(NY2 / TS, NX2 / TS), 256, SMEM_SZ>>>(
        h1, nullptr, h2, w3, b3, NX2, NY2, 2 * NY1, 2, 0, nullptr, nullptr);
    // K4: level-1 conv (w4), input = h1 + up(h2): -> h1c
    conv_t<2, false><<<dim3(NY1 / TS, NX1 / TS), 256, SMEM_SZ>>>(
        h1, h2, h1c, w4, b4, NX1, NY1, NY1, 1, N2 / 2, nullptr, nullptr);
    // K5: level-0 conv (w5) + fc2, input = h + up(h1c): -> out [N0,2]
    conv_t<2, true><<<dim3(NY0 / TS, NX0 / TS), 256, SMEM_SZ>>>(
        h, h1c, out, w5, b5, NX0, NY0, NY0, 1, N1 / 2, f2w, f2b);
}

// round 9
// speedup vs baseline: 1.0392x; 1.0392x over previous
#include <cuda_runtime.h>

#define NX0 512
#define NY0 1024
#define N0 (NX0*NY0)
#define NX1 256
#define NY1 512
#define N1 (NX1*NY1)
#define NX2 128
#define NY2 256
#define N2 (NX2*NY2)

#define TSX 32
#define TSY 32
#define HW  (TSX+2)            // 34
#define HALO_ROWS (HW*HW)      // 1156
#define ROWP_U 17              // u64 per halo row (34 floats, 2-way max conflicts)
// dynamic smem layout (bytes)
#define OFF_W    0             // 512 u64 (4096 B)  W as channel-pairs
#define OFF_B    4096          // 16 u64  (128 B)
#define OFF_FC1  4224          // 160 f   (640 B)
#define OFF_FC2  4864          // 272 B pad
#define OFF_HALO 5136
#define SMEM_SZ  (OFF_HALO + HALO_ROWS*ROWP_U*8)   // 5136 + 157216 = 162352

// Scratch (device globals; allocation-free per harness rules)
__device__ float g_h  [N0*32];
__device__ float g_h1 [N1*32];
__device__ float g_h2 [N2*32];
__device__ float g_h1c[N1*32];

typedef unsigned long long u64;

__device__ __forceinline__ u64 fma2(u64 a, u64 b, u64 c) {
    u64 d; asm("fma.rn.f32x2 %0, %1, %2, %3;" : "=l"(d) : "l"(a), "l"(b), "l"(c)); return d;
}
__device__ __forceinline__ u64 mul2(u64 a, u64 b) {
    u64 d; asm("mul.rn.f32x2 %0, %1, %2;" : "=l"(d) : "l"(a), "l"(b)); return d;
}
__device__ __forceinline__ u64 pack2(float lo, float hi) {
    u64 d; asm("mov.b64 %0, {%1, %2};" : "=l"(d) : "f"(lo), "f"(hi)); return d;
}
__device__ __forceinline__ void unpack2(u64 v, float& lo, float& hi) {
    asm("mov.b64 {%0, %1}, %2;" : "=f"(lo), "=f"(hi) : "l"(v));
}

__device__ __forceinline__ float dinvf(int ix, int iy, int nx, int ny) {
    int d = 1 + (ix > 0) + (ix < nx - 1) + (iy > 0) + (iy < ny - 1);
    return rsqrtf((float)d);
}

// MODE: 0 = RAW (rows at (hx*rs+hy*cs)*32; handles stride-2 downsample)
//       1 = FC1 (halo rows = relu(x@fc1w + fc1b), x is [N0,4])
//       2 = UPADD (halo rows = in0[p] + buffer-exact upsample gather from in1)
// FC2 : fuse final [32,2] projection, write float2 per node.
template<int MODE, bool FC2>
__global__ void __launch_bounds__(256) conv_t(
        const float* __restrict__ in0, const float* __restrict__ in1,
        float* __restrict__ out,
        const float* __restrict__ w, const float* __restrict__ b,
        int nx, int ny, int rs, int cs, int nchalf,
        const float* __restrict__ f2w, const float* __restrict__ f2b) {
    extern __shared__ __align__(16) char smem[];
    u64*   swp  = (u64*)(smem + OFF_W);
    u64*   sbp  = (u64*)(smem + OFF_B);
    float* sfc1 = (float*)(smem + OFF_FC1);
    float* sfc2 = (float*)(smem + OFF_FC2);
    u64*   halo = (u64*)(smem + OFF_HALO);
    u64*   aggT = halo;           // overlaid after B1 (sync-protected)

    int t = threadIdx.x;

    // --- weights/biases into smem ---
    {
        const u64* wp = (const u64*)w;     // row-major [32][32] -> channel pairs
        swp[t]       = wp[t];
        swp[t + 256] = wp[t + 256];
        if (t < 16) sbp[t] = ((const u64*)b)[t];
    }
    if (MODE == 1) {
        if (t < 128) sfc1[t]       = f2w[t];   // fc1_w [4][32] (passed via f2w)
        if (t < 32)  sfc1[128 + t] = f2b[t];   // fc1_b
    }
    if (FC2) {
        if (t < 64) sfc2[t]      = f2w[t];
        if (t < 2)  sfc2[64 + t] = f2b[t];
    }
    __syncthreads();

    int bx = (int)blockIdx.y;
    int by = (int)blockIdx.x;

    // --- phase A: fill halo (each row loaded/computed once per block) ---
    for (int rr = t; rr < HALO_ROWS; rr += 256) {
        int hx = bx * TSX - 1 + rr / HW;
        int hy = by * TSY - 1 + rr % HW;
        u64* dst = halo + rr * ROWP_U;
        if (hx < 0 || hx >= nx || hy < 0 || hy >= ny) {
#pragma unroll
            for (int q = 0; q < 16; q++) dst[q] = 0ull;
        } else if (MODE == 0) {
            const float4* src = (const float4*)(in0 + ((size_t)hx * rs + (size_t)hy * cs) * 32);
#pragma unroll
            for (int q = 0; q < 8; q++) {
                float4 v = src[q];
                dst[2 * q]     = pack2(v.x, v.y);
                dst[2 * q + 1] = pack2(v.z, v.w);
            }
        } else if (MODE == 1) {
            float4 xi = ((const float4*)in0)[hx * NY0 + hy];
#pragma unroll
            for (int q = 0; q < 8; q++) {
                float o[4];
#pragma unroll
                for (int u = 0; u < 4; u++) {
                    int j = 4 * q + u;
                    float a = sfc1[128 + j];
                    a = fmaf(xi.x, sfc1[j],      a);
                    a = fmaf(xi.y, sfc1[32 + j], a);
                    a = fmaf(xi.z, sfc1[64 + j], a);
                    a = fmaf(xi.w, sfc1[96 + j], a);
                    o[u] = fmaxf(a, 0.f);
                }
                dst[2 * q]     = pack2(o[0], o[1]);
                dst[2 * q + 1] = pack2(o[2], o[3]);
            }
        } else {  // UPADD
            int p = hx * ny + hy;
            const float4* hf4 = (const float4*)(in0 + (size_t)p * 32);
            int boff = 16 * (p & 1);
            const float4* c0 = (const float4*)(in1 + (size_t)(p >> 3) * 32 + boff);
            const float4* c1 = (const float4*)(in1 + ((size_t)nchalf + (p >> 3)) * 32 + boff);
#pragma unroll
            for (int j4 = 0; j4 < 4; j4++) {
                float4 a  = hf4[2 * j4], bb = hf4[2 * j4 + 1];
                float4 x0 = c0[j4],      x1 = c1[j4];
                dst[4 * j4]     = pack2(a.x + x0.x, a.y + x1.x);
                dst[4 * j4 + 1] = pack2(a.z + x0.y, a.w + x1.y);
                dst[4 * j4 + 2] = pack2(bb.x + x0.z, bb.y + x1.z);
                dst[4 * j4 + 3] = pack2(bb.z + x0.w, bb.w + x1.w);
            }
        }
    }
    __syncthreads();

    // --- phase B1: aggregate stencil for 4 vertically-adjacent nodes/thread ---
    int lx0 = 4 * (t >> 5);
    int ly  = t & 31;
    int gy  = by * TSY + ly;
    int gx0 = bx * TSX + lx0;

    u64 agg[4][16];
#pragma unroll
    for (int r = 0; r < 4; r++)
#pragma unroll
        for (int q = 0; q < 16; q++) agg[r][q] = 0ull;

    // center-column rows (shared by up to 3 nodes)
#pragma unroll
    for (int cx = 0; cx < 6; cx++) {
        const u64* row = halo + ((lx0 + cx) * HW + (ly + 1)) * ROWP_U;
        float s = dinvf(gx0 + cx - 1, gy, nx, ny);
        u64 sp = pack2(s, s);
#pragma unroll
        for (int r = 0; r < 4; r++) {
            if (r >= cx - 2 && r <= cx) {
#pragma unroll
                for (int q = 0; q < 16; q++) agg[r][q] = fma2(sp, row[q], agg[r][q]);
            }
        }
    }
    // side rows (y-1, y+1), one per node
#pragma unroll
    for (int r = 0; r < 4; r++) {
        int hx = lx0 + r + 1;
        const u64* rm = halo + (hx * HW + ly)     * ROWP_U;
        const u64* rp = halo + (hx * HW + ly + 2) * ROWP_U;
        float sm = dinvf(gx0 + r, gy - 1, nx, ny);
        float sp = dinvf(gx0 + r, gy + 1, nx, ny);
        u64 smp = pack2(sm, sm), spp = pack2(sp, sp);
#pragma unroll
        for (int q = 0; q < 16; q++) agg[r][q] = fma2(smp, rm[q], agg[r][q]);
#pragma unroll
        for (int q = 0; q < 16; q++) agg[r][q] = fma2(spp, rp[q], agg[r][q]);
    }
#pragma unroll
    for (int r = 0; r < 4; r++) {
        float sC = dinvf(gx0 + r, gy, nx, ny);
        u64 sCp = pack2(sC, sC);
#pragma unroll
        for (int q = 0; q < 16; q++) agg[r][q] = mul2(agg[r][q], sCp);
    }
    __syncthreads();   // halo reads done; safe to overlay

    // store transposed: aggT[kp*1024 + node], node = (lx0+r)*32 + ly (8B lane stride)
#pragma unroll
    for (int r = 0; r < 4; r++) {
        int n = (lx0 + r) * TSY + ly;
#pragma unroll
        for (int kp = 0; kp < 16; kp++) aggT[kp * (TSX * TSY) + n] = agg[r][kp];
    }
    __syncthreads();

    // --- phase B2: matmul, 4 nodes/thread, weights amortized 4x ---
    float o0[4], o1[4];
    if (FC2) {
#pragma unroll
        for (int r = 0; r < 4; r++) { o0[r] = sfc2[64]; o1[r] = sfc2[65]; }
    }
    int nbase = lx0 * TSY + ly;

#pragma unroll
    for (int half = 0; half < 2; half++) {
        u64 acc[4][8];
#pragma unroll
        for (int r = 0; r < 4; r++)
#pragma unroll
            for (int q = 0; q < 8; q++) acc[r][q] = sbp[half * 8 + q];

#pragma unroll
        for (int kp = 0; kp < 16; kp++) {
            u64 a0p[4], a1p[4];
#pragma unroll
            for (int r = 0; r < 4; r++) {
                u64 av = aggT[kp * (TSX * TSY) + nbase + r * TSY];
                float x0, x1; unpack2(av, x0, x1);
                a0p[r] = pack2(x0, x0);
                a1p[r] = pack2(x1, x1);
            }
            const u64* wrow = swp + 2 * kp * 16 + half * 8;
#pragma unroll
            for (int q = 0; q < 8; q++) {
                u64 w0 = wrow[q];
#pragma unroll
                for (int r = 0; r < 4; r++) acc[r][q] = fma2(a0p[r], w0, acc[r][q]);
            }
#pragma unroll
            for (int q = 0; q < 8; q++) {
                u64 w1 = wrow[16 + q];
#pragma unroll
                for (int r = 0; r < 4; r++) acc[r][q] = fma2(a1p[r], w1, acc[r][q]);
            }
        }

        // relu + store (or fc2 accumulate) for channels [half*16, half*16+16)
#pragma unroll
        for (int r = 0; r < 4; r++) {
            float v[16];
#pragma unroll
            for (int q = 0; q < 8; q++) {
                float x0, x1; unpack2(acc[r][q], x0, x1);
                v[2 * q]     = fmaxf(x0, 0.f);
                v[2 * q + 1] = fmaxf(x1, 0.f);
            }
            if (!FC2) {
                int gx = gx0 + r;
                float4* o = (float4*)(out + ((size_t)gx * ny + gy) * 32 + half * 16);
#pragma unroll
                for (int j = 0; j < 4; j++)
                    o[j] = make_float4(v[4 * j], v[4 * j + 1], v[4 * j + 2], v[4 * j + 3]);
            } else {
#pragma unroll
                for (int q = 0; q < 16; q++) {
                    int c = half * 16 + q;
                    o0[r] = fmaf(v[q], sfc2[2 * c],     o0[r]);
                    o1[r] = fmaf(v[q], sfc2[2 * c + 1], o1[r]);
                }
            }
        }
    }
    if (FC2) {
#pragma unroll
        for (int r = 0; r < 4; r++) {
            int gx = gx0 + r;
            ((float2*)out)[(size_t)gx * ny + gy] = make_float2(o0[r], o1[r]);
        }
    }
}

extern "C" void kernel_launch(void* const* d_in, const int* in_sizes, int n_in,
                              void* d_out, int out_size) {
    const float* x    = (const float*)d_in[0];
    // d_in[1..3]: edge_index_* — unused (regular grid, stencil is analytic)
    const float* fc1w = (const float*)d_in[4];
    const float* fc1b = (const float*)d_in[5];
    const float* w1 = (const float*)d_in[6];  const float* b1 = (const float*)d_in[7];
    const float* w2 = (const float*)d_in[8];  const float* b2 = (const float*)d_in[9];
    const float* w3 = (const float*)d_in[10]; const float* b3 = (const float*)d_in[11];
    const float* w4 = (const float*)d_in[12]; const float* b4 = (const float*)d_in[13];
    const float* w5 = (const float*)d_in[14]; const float* b5 = (const float*)d_in[15];
    const float* f2w = (const float*)d_in[16]; const float* f2b = (const float*)d_in[17];
    float* out = (float*)d_out;

    void* p;
    cudaGetSymbolAddress(&p, g_h);   float* h   = (float*)p;
    cudaGetSymbolAddress(&p, g_h1);  float* h1  = (float*)p;
    cudaGetSymbolAddress(&p, g_h2);  float* h2  = (float*)p;
    cudaGetSymbolAddress(&p, g_h1c); float* h1c = (float*)p;

    cudaFuncSetAttribute(conv_t<1, false>, cudaFuncAttributeMaxDynamicSharedMemorySize, SMEM_SZ);
    cudaFuncSetAttribute(conv_t<0, false>, cudaFuncAttributeMaxDynamicSharedMemorySize, SMEM_SZ);
    cudaFuncSetAttribute(conv_t<2, false>, cudaFuncAttributeMaxDynamicSharedMemorySize, SMEM_SZ);
    cudaFuncSetAttribute(conv_t<2, true >, cudaFuncAttributeMaxDynamicSharedMemorySize, SMEM_SZ);

    // K1: fc1 + level-0 conv (w1): x -> h
    conv_t<1, false><<<dim3(NY0 / TSY, NX0 / TSX), 256, SMEM_SZ>>>(
        x, nullptr, h, w1, b1, NX0, NY0, NY0, 1, 0, fc1w, fc1b);
    // K2: level-1 conv (w2), input = h downsampled (stride 2): h -> h1
    conv_t<0, false><<<dim3(NY1 / TSY, NX1 / TSX), 256, SMEM_SZ>>>(
        h, nullptr, h1, w2, b2, NX1, NY1, 2 * NY0, 2, 0, nullptr, nullptr);
    // K3: level-2 conv (w3), input = h1 downsampled: h1 -> h2
    conv_t<0, false><<<dim3(NY2 / TSY, NX2 / TSX), 256, SMEM_SZ>>>(
        h1, nullptr, h2, w3, b3, NX2, NY2, 2 * NY1, 2, 0, nullptr, nullptr);
    // K4: level-1 conv (w4), input = h1 + up(h2): -> h1c
    conv_t<2, false><<<dim3(NY1 / TSY, NX1 / TSX), 256, SMEM_SZ>>>(
        h1, h2, h1c, w4, b4, NX1, NY1, NY1, 1, N2 / 2, nullptr, nullptr);
    // K5: level-0 conv (w5) + fc2, input = h + up(h1c): -> out [N0,2]
    conv_t<2, true><<<dim3(NY0 / TSY, NX0 / TSX), 256, SMEM_SZ>>>(
        h, h1c, out, w5, b5, NX0, NY0, NY0, 1, N1 / 2, f2w, f2b);
}

// round 10
// speedup vs baseline: 1.1737x; 1.1294x over previous
#include <cuda_runtime.h>

#define NX0 512
#define NY0 1024
#define N0 (NX0*NY0)
#define NX1 256
#define NY1 512
#define N1 (NX1*NY1)
#define NX2 128
#define NY2 256
#define N2 (NX2*NY2)

#define TSX 16                 // tile rows (x)
#define TSY 32                 // tile cols (y)
#define HWX (TSX+2)            // 18
#define HWY (TSY+2)            // 34
#define HALO_ROWS (HWX*HWY)    // 612
#define ROWP_U 17              // u64 per halo row (34 floats)
#define TNODES (TSX*TSY)       // 512 nodes per tile
// dynamic smem layout (bytes)
#define OFF_W    0             // 512 u64 (4096 B)  W as channel-pairs
#define OFF_B    4096          // 16 u64  (128 B)
#define OFF_FC1  4224          // 160 f   (640 B)
#define OFF_FC2  4864          // 272 B pad
#define OFF_HALO 5136
#define SMEM_SZ  (OFF_HALO + HALO_ROWS*ROWP_U*8)   // 5136 + 83232 = 88368 (2 CTAs/SM)

// Scratch (device globals; allocation-free per harness rules)
__device__ float g_h  [N0*32];
__device__ float g_h1 [N1*32];
__device__ float g_h2 [N2*32];
__device__ float g_h1c[N1*32];

typedef unsigned long long u64;

__device__ __forceinline__ u64 fma2(u64 a, u64 b, u64 c) {
    u64 d; asm("fma.rn.f32x2 %0, %1, %2, %3;" : "=l"(d) : "l"(a), "l"(b), "l"(c)); return d;
}
__device__ __forceinline__ u64 mul2(u64 a, u64 b) {
    u64 d; asm("mul.rn.f32x2 %0, %1, %2;" : "=l"(d) : "l"(a), "l"(b)); return d;
}
__device__ __forceinline__ u64 pack2(float lo, float hi) {
    u64 d; asm("mov.b64 %0, {%1, %2};" : "=l"(d) : "f"(lo), "f"(hi)); return d;
}
__device__ __forceinline__ void unpack2(u64 v, float& lo, float& hi) {
    asm("mov.b64 {%0, %1}, %2;" : "=f"(lo), "=f"(hi) : "l"(v));
}

__device__ __forceinline__ float dinvf(int ix, int iy, int nx, int ny) {
    int d = 1 + (ix > 0) + (ix < nx - 1) + (iy > 0) + (iy < ny - 1);
    return rsqrtf((float)d);
}

// MODE: 0 = RAW (rows at (hx*rs+hy*cs)*32; handles stride-2 downsample)
//       1 = FC1 (halo rows = relu(x@fc1w + fc1b), x is [N0,4])
//       2 = UPADD (halo rows = in0[p] + buffer-exact upsample gather from in1)
// FC2 : fuse final [32,2] projection, write float2 per node.
template<int MODE, bool FC2>
__global__ void __launch_bounds__(256, 2) conv_t(
        const float* __restrict__ in0, const float* __restrict__ in1,
        float* __restrict__ out,
        const float* __restrict__ w, const float* __restrict__ b,
        int nx, int ny, int rs, int cs, int nchalf,
        const float* __restrict__ f2w, const float* __restrict__ f2b) {
    extern __shared__ __align__(16) char smem[];
    u64*   swp  = (u64*)(smem + OFF_W);
    u64*   sbp  = (u64*)(smem + OFF_B);
    float* sfc1 = (float*)(smem + OFF_FC1);
    float* sfc2 = (float*)(smem + OFF_FC2);
    u64*   halo = (u64*)(smem + OFF_HALO);
    u64*   aggT = halo;           // overlaid after B1 (sync-protected, 64KB <= 83KB)

    int t = threadIdx.x;

    // --- weights/biases into smem ---
    {
        const u64* wp = (const u64*)w;     // row-major [32][32] -> channel pairs
        swp[t]       = wp[t];
        swp[t + 256] = wp[t + 256];
        if (t < 16) sbp[t] = ((const u64*)b)[t];
    }
    if (MODE == 1) {
        if (t < 128) sfc1[t]       = f2w[t];   // fc1_w [4][32] (passed via f2w)
        if (t < 32)  sfc1[128 + t] = f2b[t];   // fc1_b
    }
    if (FC2) {
        if (t < 64) sfc2[t]      = f2w[t];
        if (t < 2)  sfc2[64 + t] = f2b[t];
    }
    __syncthreads();

    int bx = (int)blockIdx.y;
    int by = (int)blockIdx.x;

    // --- phase A: fill halo (each row loaded/computed once per block) ---
    for (int rr = t; rr < HALO_ROWS; rr += 256) {
        int hx = bx * TSX - 1 + rr / HWY;
        int hy = by * TSY - 1 + rr % HWY;
        u64* dst = halo + rr * ROWP_U;
        if (hx < 0 || hx >= nx || hy < 0 || hy >= ny) {
#pragma unroll
            for (int q = 0; q < 16; q++) dst[q] = 0ull;
        } else if (MODE == 0) {
            const float4* src = (const float4*)(in0 + ((size_t)hx * rs + (size_t)hy * cs) * 32);
#pragma unroll
            for (int q = 0; q < 8; q++) {
                float4 v = src[q];
                dst[2 * q]     = pack2(v.x, v.y);
                dst[2 * q + 1] = pack2(v.z, v.w);
            }
        } else if (MODE == 1) {
            float4 xi = ((const float4*)in0)[hx * NY0 + hy];
#pragma unroll
            for (int q = 0; q < 8; q++) {
                float o[4];
#pragma unroll
                for (int u = 0; u < 4; u++) {
                    int j = 4 * q + u;
                    float a = sfc1[128 + j];
                    a = fmaf(xi.x, sfc1[j],      a);
                    a = fmaf(xi.y, sfc1[32 + j], a);
                    a = fmaf(xi.z, sfc1[64 + j], a);
                    a = fmaf(xi.w, sfc1[96 + j], a);
                    o[u] = fmaxf(a, 0.f);
                }
                dst[2 * q]     = pack2(o[0], o[1]);
                dst[2 * q + 1] = pack2(o[2], o[3]);
            }
        } else {  // UPADD
            int p = hx * ny + hy;
            const float4* hf4 = (const float4*)(in0 + (size_t)p * 32);
            int boff = 16 * (p & 1);
            const float4* c0 = (const float4*)(in1 + (size_t)(p >> 3) * 32 + boff);
            const float4* c1 = (const float4*)(in1 + ((size_t)nchalf + (p >> 3)) * 32 + boff);
#pragma unroll
            for (int j4 = 0; j4 < 4; j4++) {
                float4 a  = hf4[2 * j4], bb = hf4[2 * j4 + 1];
                float4 x0 = c0[j4],      x1 = c1[j4];
                dst[4 * j4]     = pack2(a.x + x0.x, a.y + x1.x);
                dst[4 * j4 + 1] = pack2(a.z + x0.y, a.w + x1.y);
                dst[4 * j4 + 2] = pack2(bb.x + x0.z, bb.y + x1.z);
                dst[4 * j4 + 3] = pack2(bb.z + x0.w, bb.w + x1.w);
            }
        }
    }
    __syncthreads();

    // --- phase B1: aggregate stencil, 2 vertically-adjacent nodes/thread ---
    int lx0 = 2 * (t >> 5);        // 0..14
    int ly  = t & 31;
    int gy  = by * TSY + ly;
    int gx0 = bx * TSX + lx0;

    u64 agg[2][16];
#pragma unroll
    for (int r = 0; r < 2; r++)
#pragma unroll
        for (int q = 0; q < 16; q++) agg[r][q] = 0ull;

    // center-column rows (4 rows, shared between the 2 nodes)
#pragma unroll
    for (int cx = 0; cx < 4; cx++) {
        const u64* row = halo + ((lx0 + cx) * HWY + (ly + 1)) * ROWP_U;
        float s = dinvf(gx0 + cx - 1, gy, nx, ny);
        u64 sp = pack2(s, s);
#pragma unroll
        for (int r = 0; r < 2; r++) {
            if (r >= cx - 2 && r <= cx) {
#pragma unroll
                for (int q = 0; q < 16; q++) agg[r][q] = fma2(sp, row[q], agg[r][q]);
            }
        }
    }
    // side rows (y-1, y+1), one pair per node
#pragma unroll
    for (int r = 0; r < 2; r++) {
        int hx = lx0 + r + 1;
        const u64* rm = halo + (hx * HWY + ly)     * ROWP_U;
        const u64* rp = halo + (hx * HWY + ly + 2) * ROWP_U;
        float sm = dinvf(gx0 + r, gy - 1, nx, ny);
        float sp = dinvf(gx0 + r, gy + 1, nx, ny);
        u64 smp = pack2(sm, sm), spp = pack2(sp, sp);
#pragma unroll
        for (int q = 0; q < 16; q++) agg[r][q] = fma2(smp, rm[q], agg[r][q]);
#pragma unroll
        for (int q = 0; q < 16; q++) agg[r][q] = fma2(spp, rp[q], agg[r][q]);
    }
#pragma unroll
    for (int r = 0; r < 2; r++) {
        float sC = dinvf(gx0 + r, gy, nx, ny);
        u64 sCp = pack2(sC, sC);
#pragma unroll
        for (int q = 0; q < 16; q++) agg[r][q] = mul2(agg[r][q], sCp);
    }
    __syncthreads();   // halo reads done; safe to overlay

    // store transposed: aggT[kp*512 + node], node = (lx0+r)*32 + ly
#pragma unroll
    for (int r = 0; r < 2; r++) {
        int n = (lx0 + r) * TSY + ly;
#pragma unroll
        for (int kp = 0; kp < 16; kp++) aggT[kp * TNODES + n] = agg[r][kp];
    }
    __syncthreads();

    // --- phase B2: matmul, 2 nodes/thread, weights amortized 2x ---
    float o0[2], o1[2];
    if (FC2) {
#pragma unroll
        for (int r = 0; r < 2; r++) { o0[r] = sfc2[64]; o1[r] = sfc2[65]; }
    }
    int nbase = lx0 * TSY + ly;

#pragma unroll
    for (int half = 0; half < 2; half++) {
        u64 acc[2][8];
#pragma unroll
        for (int r = 0; r < 2; r++)
#pragma unroll
            for (int q = 0; q < 8; q++) acc[r][q] = sbp[half * 8 + q];

#pragma unroll
        for (int kp = 0; kp < 16; kp++) {
            u64 a0p[2], a1p[2];
#pragma unroll
            for (int r = 0; r < 2; r++) {
                u64 av = aggT[kp * TNODES + nbase + r * TSY];
                float x0, x1; unpack2(av, x0, x1);
                a0p[r] = pack2(x0, x0);
                a1p[r] = pack2(x1, x1);
            }
            const u64* wrow = swp + 2 * kp * 16 + half * 8;
#pragma unroll
            for (int q = 0; q < 8; q++) {
                u64 w0 = wrow[q];
#pragma unroll
                for (int r = 0; r < 2; r++) acc[r][q] = fma2(a0p[r], w0, acc[r][q]);
            }
#pragma unroll
            for (int q = 0; q < 8; q++) {
                u64 w1 = wrow[16 + q];
#pragma unroll
                for (int r = 0; r < 2; r++) acc[r][q] = fma2(a1p[r], w1, acc[r][q]);
            }
        }

        // relu + store (or fc2 accumulate) for channels [half*16, half*16+16)
#pragma unroll
        for (int r = 0; r < 2; r++) {
            float v[16];
#pragma unroll
            for (int q = 0; q < 8; q++) {
                float x0, x1; unpack2(acc[r][q], x0, x1);
                v[2 * q]     = fmaxf(x0, 0.f);
                v[2 * q + 1] = fmaxf(x1, 0.f);
            }
            if (!FC2) {
                int gx = gx0 + r;
                float4* o = (float4*)(out + ((size_t)gx * ny + gy) * 32 + half * 16);
#pragma unroll
                for (int j = 0; j < 4; j++)
                    o[j] = make_float4(v[4 * j], v[4 * j + 1], v[4 * j + 2], v[4 * j + 3]);
            } else {
#pragma unroll
                for (int q = 0; q < 16; q++) {
                    int c = half * 16 + q;
                    o0[r] = fmaf(v[q], sfc2[2 * c],     o0[r]);
                    o1[r] = fmaf(v[q], sfc2[2 * c + 1], o1[r]);
                }
            }
        }
    }
    if (FC2) {
#pragma unroll
        for (int r = 0; r < 2; r++) {
            int gx = gx0 + r;
            ((float2*)out)[(size_t)gx * ny + gy] = make_float2(o0[r], o1[r]);
        }
    }
}

extern "C" void kernel_launch(void* const* d_in, const int* in_sizes, int n_in,
                              void* d_out, int out_size) {
    const float* x    = (const float*)d_in[0];
    // d_in[1..3]: edge_index_* — unused (regular grid, stencil is analytic)
    const float* fc1w = (const float*)d_in[4];
    const float* fc1b = (const float*)d_in[5];
    const float* w1 = (const float*)d_in[6];  const float* b1 = (const float*)d_in[7];
    const float* w2 = (const float*)d_in[8];  const float* b2 = (const float*)d_in[9];
    const float* w3 = (const float*)d_in[10]; const float* b3 = (const float*)d_in[11];
    const float* w4 = (const float*)d_in[12]; const float* b4 = (const float*)d_in[13];
    const float* w5 = (const float*)d_in[14]; const float* b5 = (const float*)d_in[15];
    const float* f2w = (const float*)d_in[16]; const float* f2b = (const float*)d_in[17];
    float* out = (float*)d_out;

    void* p;
    cudaGetSymbolAddress(&p, g_h);   float* h   = (float*)p;
    cudaGetSymbolAddress(&p, g_h1);  float* h1  = (float*)p;
    cudaGetSymbolAddress(&p, g_h2);  float* h2  = (float*)p;
    cudaGetSymbolAddress(&p, g_h1c); float* h1c = (float*)p;

    cudaFuncSetAttribute(conv_t<1, false>, cudaFuncAttributeMaxDynamicSharedMemorySize, SMEM_SZ);
    cudaFuncSetAttribute(conv_t<0, false>, cudaFuncAttributeMaxDynamicSharedMemorySize, SMEM_SZ);
    cudaFuncSetAttribute(conv_t<2, false>, cudaFuncAttributeMaxDynamicSharedMemorySize, SMEM_SZ);
    cudaFuncSetAttribute(conv_t<2, true >, cudaFuncAttributeMaxDynamicSharedMemorySize, SMEM_SZ);

    // K1: fc1 + level-0 conv (w1): x -> h
    conv_t<1, false><<<dim3(NY0 / TSY, NX0 / TSX), 256, SMEM_SZ>>>(
        x, nullptr, h, w1, b1, NX0, NY0, NY0, 1, 0, fc1w, fc1b);
    // K2: level-1 conv (w2), input = h downsampled (stride 2): h -> h1
    conv_t<0, false><<<dim3(NY1 / TSY, NX1 / TSX), 256, SMEM_SZ>>>(
        h, nullptr, h1, w2, b2, NX1, NY1, 2 * NY0, 2, 0, nullptr, nullptr);
    // K3: level-2 conv (w3), input = h1 downsampled: h1 -> h2
    conv_t<0, false><<<dim3(NY2 / TSY, NX2 / TSX), 256, SMEM_SZ>>>(
        h1, nullptr, h2, w3, b3, NX2, NY2, 2 * NY1, 2, 0, nullptr, nullptr);
    // K4: level-1 conv (w4), input = h1 + up(h2): -> h1c
    conv_t<2, false><<<dim3(NY1 / TSY, NX1 / TSX), 256, SMEM_SZ>>>(
        h1, h2, h1c, w4, b4, NX1, NY1, NY1, 1, N2 / 2, nullptr, nullptr);
    // K5: level-0 conv (w5) + fc2, input = h + up(h1c): -> out [N0,2]
    conv_t<2, true><<<dim3(NY0 / TSY, NX0 / TSX), 256, SMEM_SZ>>>(
        h, h1c, out, w5, b5, NX0, NY0, NY0, 1, N1 / 2, f2w, f2b);
}